// round 11
// baseline (speedup 1.0000x reference)
#include <cuda_runtime.h>

// LSTM: B=2048, T=512, I=1, H=64, gates=256 (i,f,g,o), O=1. fp32 throughout.
// Grid: 296 CTAs x 256 threads = 2 CTAs/SM (one balanced wave), 512 thr/SM
// -> 4 warps per SMSP (vs 2 before) at the SAME fma-pipe floor, for latency
// hiding. Each CTA owns RPB=7 batch rows for the full T=512 recurrence.
//
// K-split ownership: warp w covers cells m in [8w, 8w+8). Lane l:
//   p = l&15, half = l>>4 (k-range: half*32..half*32+32)
//   q = p>>3: q=0 -> gate rows (i,f) of cell m=8w+(p&7); q=1 -> (g,o)
// Each lane holds HALF of W_hh for its two gate rows (32 u64 = 64 regs) and
// accumulates k-partials via fma.rn.f32x2 (14 chains). Partials combine with
// ONE shfl.xor(16) per row (halves swap opposite gates). half0 activates
// gate A, half1 gate B (branchless). Cell update gathers f/g/o via
// shfl.xor(16/8/24). h double-buffered in SMEM: ONE __syncthreads per step.

#define BATCH  2048
#define TSTEPS 512
#define HID    64
#define RPB    7
#define NTHR   256
#define GRID   296   // 2 x 148 SMs; 296*7 = 2072 >= 2048 (tail clamped)

typedef unsigned long long u64;

__device__ __forceinline__ void fma2(u64 &acc, u64 a, u64 b) {
    asm("fma.rn.f32x2 %0, %1, %2, %0;" : "+l"(acc) : "l"(a), "l"(b));
}

__device__ __forceinline__ float2 unpack2(u64 v) {
    float2 r;
    asm("mov.b64 {%0, %1}, %2;" : "=f"(r.x), "=f"(r.y) : "l"(v));
    return r;
}

__device__ __forceinline__ float ex2f(float x) {
    float e;
    asm("ex2.approx.f32 %0, %1;" : "=f"(e) : "f"(x));
    return e;
}
__device__ __forceinline__ float rcpf(float x) {
    float r;
    asm("rcp.approx.f32 %0, %1;" : "=f"(r) : "f"(x));
    return r;
}

// tanh(x) = 1 - 2/(1 + 2^(2x*log2e)); saturates correctly at +-inf.
__device__ __forceinline__ float fast_tanh(float x) {
    return fmaf(-2.0f, rcpf(1.0f + ex2f(x * 2.8853900817779268f)), 1.0f);
}

__global__ __launch_bounds__(NTHR, 2)
void lstm_fused_kernel(const float* __restrict__ x,      // [B, T, 1]
                       const float* __restrict__ w_ih,   // [256, 1]
                       const float* __restrict__ w_hh,   // [256, 64]
                       const float* __restrict__ b_ih,   // [256]
                       const float* __restrict__ b_hh,   // [256]
                       const float* __restrict__ w_lin,  // [1, 64]
                       const float* __restrict__ b_lin,  // [1]
                       float* __restrict__ out)          // [B, 1]
{
    __shared__ float sh_x[RPB * TSTEPS];      // 14 KB
    __shared__ float sh_h[2][RPB][HID];       // 3.5 KB, double-buffered

    const int t    = threadIdx.x;
    const int l    = t & 31;
    const int w    = t >> 5;                  // warp 0..7
    const int p    = l & 15;
    const int half = l >> 4;                  // k-range half
    const int q    = p >> 3;                  // 0: (i,f)  1: (g,o)
    const int m    = (w << 3) + (p & 7);      // cell 0..63
    const int b0   = blockIdx.x * RPB;

    const int jA = m + (q ? 128 : 0);         // i (q=0) or g (q=1)
    const int jB = jA + 64;                   // f (q=0) or o (q=1)

    // ---- half of W_hh for rows jA, jB: 2 x 16 u64 = 64 regs ----
    u64 wA[16], wB[16];
    {
        const u64* w64 = reinterpret_cast<const u64*>(w_hh);
        const u64* pa = w64 + (size_t)jA * 32 + half * 16;
        const u64* pb = w64 + (size_t)jB * 32 + half * 16;
#pragma unroll
        for (int k = 0; k < 16; ++k) { wA[k] = pa[k]; wB[k] = pb[k]; }
    }

    // This lane activates gate jSel (half0 -> A, half1 -> B).
    const int jSel = half ? jB : jA;
    const float wihS  = w_ih[jSel];
    const float biasS = b_ih[jSel] + b_hh[jSel];

    // Branchless activation: act = Ac * rcp(1 + ex2(Bc * x)) + Cc
    // tanh only for the g gate (q=1, half=0); all others sigmoid.
    const float L2E = 1.4426950408889634f;
    const bool isTanh = (q == 1) && (half == 0);
    const float Bc = isTanh ? 2.0f * L2E : -L2E;
    const float Ac = isTanh ? -2.0f : 1.0f;
    const float Cc = isTanh ? 1.0f : 0.0f;

    // ---- stage x: 7 rows x 512 steps = 896 float4, clamp row for tail CTA ----
    {
        const float4* src = reinterpret_cast<const float4*>(x);
        float4* dst = reinterpret_cast<float4*>(sh_x);
        for (int idx = t; idx < RPB * TSTEPS / 4; idx += NTHR) {
            int rl = idx >> 7;                 // 128 float4 per row
            int g  = b0 + rl;
            if (g > BATCH - 1) g = BATCH - 1;  // clamp (garbage rows unused)
            dst[idx] = src[(size_t)g * (TSTEPS / 4) + (idx & 127)];
        }
    }
    // init h buffer 0 = 0
    for (int i = t; i < RPB * HID; i += NTHR)
        (&sh_h[0][0][0])[i] = 0.0f;

    float c[RPB];
#pragma unroll
    for (int r = 0; r < RPB; ++r) c[r] = 0.0f;

    __syncthreads();

    for (int step = 0; step < TSTEPS; ++step) {
        const int rb = step & 1;               // read buffer
        const int wb = rb ^ 1;                 // write buffer

        // ---------- k-half partial dots: f32x2, 14 independent chains ----------
        u64 aA[RPB], aB[RPB];
#pragma unroll
        for (int r = 0; r < RPB; ++r) { aA[r] = 0ull; aB[r] = 0ull; }

        const ulonglong2* hbase =
            reinterpret_cast<const ulonglong2*>(&sh_h[rb][0][half * 32]);
#pragma unroll
        for (int kk = 0; kk < 8; ++kk) {       // 8 x LDS.128 per row
            ulonglong2 hv[RPB];
#pragma unroll
            for (int r = 0; r < RPB; ++r)
                hv[r] = hbase[r * (HID / 4) + kk];
#pragma unroll
            for (int r = 0; r < RPB; ++r) {
                fma2(aA[r], hv[r].x, wA[2 * kk]);
                fma2(aA[r], hv[r].y, wA[2 * kk + 1]);
                fma2(aB[r], hv[r].x, wB[2 * kk]);
                fma2(aB[r], hv[r].y, wB[2 * kk + 1]);
            }
        }

        // ---------- combine halves (1 shfl/row) + activate (1 act/lane) ----------
        float act[RPB];
#pragma unroll
        for (int r = 0; r < RPB; ++r) {
            float2 pa = unpack2(aA[r]);
            float2 pb = unpack2(aB[r]);
            float sA = pa.x + pa.y;
            float sB = pb.x + pb.y;
            // half0 keeps A and needs partner's A; half1 keeps B, needs B.
            float send = half ? sA : sB;
            float recv = __shfl_xor_sync(0xFFFFFFFFu, send, 16);
            float sOwn = half ? sB : sA;
            float xv = sh_x[r * TSTEPS + step];
            float pre = (sOwn + recv) + fmaf(xv, wihS, biasS);
            act[r] = fmaf(Ac, rcpf(1.0f + ex2f(pre * Bc)), Cc);
        }

        // ---------- gather f/g/o via shfl, update c/h on owner lanes ----------
#pragma unroll
        for (int r = 0; r < RPB; ++r) {
            // owner lane l<8: act = sigmoid(i). Partners:
            //   l^16 = (q0,h1): sigmoid(f);  l^8 = (q1,h0): tanh(g);
            //   l^24 = (q1,h1): sigmoid(o)
            float fv = __shfl_xor_sync(0xFFFFFFFFu, act[r], 16);
            float gv = __shfl_xor_sync(0xFFFFFFFFu, act[r], 8);
            float ov = __shfl_xor_sync(0xFFFFFFFFu, act[r], 24);
            c[r] = fmaf(fv, c[r], act[r] * gv);
            float hval = ov * fast_tanh(c[r]);
            if (l < 8) sh_h[wb][r][m] = hval;   // one owner per (r, m)
        }
        __syncthreads();
    }

    // ---------- output projection: out[b] = h_last . w_lin + b_lin ----------
    // Last write went to buffer wb = (511 & 1) ^ 1 = 0.
    if (t < RPB && (b0 + t) < BATCH) {
        float s = b_lin[0];
#pragma unroll
        for (int k = 0; k < HID; ++k)
            s = fmaf(sh_h[0][t][k], w_lin[k], s);
        out[b0 + t] = s;
    }
}

extern "C" void kernel_launch(void* const* d_in, const int* in_sizes, int n_in,
                              void* d_out, int out_size) {
    const float* x     = (const float*)d_in[0];
    const float* w_ih  = (const float*)d_in[1];
    const float* w_hh  = (const float*)d_in[2];
    const float* b_ih  = (const float*)d_in[3];
    const float* b_hh  = (const float*)d_in[4];
    const float* w_lin = (const float*)d_in[5];
    const float* b_lin = (const float*)d_in[6];
    float* out = (float*)d_out;

    lstm_fused_kernel<<<GRID, NTHR>>>(x, w_ih, w_hh, b_ih, b_hh,
                                      w_lin, b_lin, out);
}

// round 12
// speedup vs baseline: 1.3134x; 1.3134x over previous
#include <cuda_runtime.h>

// LSTM: B=2048, T=512, I=1, H=64, gates=256 (i,f,g,o), O=1. fp32 throughout.
// Grid: 296 CTAs x 128 threads = exactly 2 CTAs per SM (one balanced wave).
// Each CTA owns RPB=7 batch rows for the full T=512 recurrence.
// (Structure = Round-10 winner; Round-11 K-split regressed and is reverted.)
//
// Cell-aligned gate ownership: warp w covers cells m in [16w, 16w+16).
//   lane l<16  owns gate rows m       (i) and m+128 (g) of cell m=16w+l
//   lane l>=16 owns gate rows m+64    (f) and m+192 (o) of cell m=16w+(l-16)
// (f,o) reach the (i,g) lane via two shfl.xor(16); h is double-buffered in
// SMEM -> ONE __syncthreads per step. W_hh rows live in registers
// (f32x2-packed), dots via fma.rn.f32x2 with 14 independent chains.
//
// NEW this round: all activations via single-instruction MUFU.TANH.
//   sigmoid(x) = 0.5 + 0.5*tanh(x/2), with the 1/2 PRE-FOLDED into the
//   register-resident W_hh rows / w_ih / bias of the sigmoid gates (i,f,o)
//   at load time -> sigmoid = 1 MUFU + 1 FFMA, tanh = 1 MUFU.
//   MUFU per warp per step: 42 -> 21, dependent chain 32 -> 16 cycles.

#define BATCH  2048
#define TSTEPS 512
#define HID    64
#define RPB    7
#define NTHR   128
#define GRID   296   // 2 x 148 SMs; 296*7 = 2072 >= 2048 (tail clamped)

typedef unsigned long long u64;

__device__ __forceinline__ void fma2(u64 &acc, u64 a, u64 b) {
    asm("fma.rn.f32x2 %0, %1, %2, %0;" : "+l"(acc) : "l"(a), "l"(b));
}

__device__ __forceinline__ float2 unpack2(u64 v) {
    float2 r;
    asm("mov.b64 {%0, %1}, %2;" : "=f"(r.x), "=f"(r.y) : "l"(v));
    return r;
}

__device__ __forceinline__ u64 pack2(float lo, float hi) {
    u64 v;
    asm("mov.b64 %0, {%1, %2};" : "=l"(v) : "f"(lo), "f"(hi));
    return v;
}

// Hardware tanh (MUFU.TANH, sm_75+). Single op, lat ~16, abs err ~2^-11.
__device__ __forceinline__ float tanh_hw(float x) {
    float r;
    asm("tanh.approx.f32 %0, %1;" : "=f"(r) : "f"(x));
    return r;
}

// Scale both packed floats of a u64 by s.
__device__ __forceinline__ u64 scale2(u64 v, float s) {
    float2 p = unpack2(v);
    return pack2(p.x * s, p.y * s);
}

__global__ __launch_bounds__(NTHR, 2)
void lstm_fused_kernel(const float* __restrict__ x,      // [B, T, 1]
                       const float* __restrict__ w_ih,   // [256, 1]
                       const float* __restrict__ w_hh,   // [256, 64]
                       const float* __restrict__ b_ih,   // [256]
                       const float* __restrict__ b_hh,   // [256]
                       const float* __restrict__ w_lin,  // [1, 64]
                       const float* __restrict__ b_lin,  // [1]
                       float* __restrict__ out)          // [B, 1]
{
    __shared__ float sh_x[RPB * TSTEPS];      // 14 KB
    __shared__ float sh_h[2][RPB][HID];       // 3.5 KB, double-buffered

    const int t  = threadIdx.x;
    const int l  = t & 31;
    const int w  = t >> 5;
    const int b0 = blockIdx.x * RPB;

    const int  m  = (w << 4) + (l & 15);      // cell this thread serves
    const bool hi = (l & 16) != 0;            // upper half-warp = (f,o) owner
    const int  jA = m + (hi ? 64 : 0);        // i-row (lo) / f-row (hi)
    const int  jB = jA + 128;                 // g-row (lo) / o-row (hi)

    // Gate A (i or f) is always sigmoid -> pre-scale its weights by 0.5.
    // Gate B: g (lo) is tanh -> no scale; o (hi) is sigmoid -> scale 0.5.
    const float sB = hi ? 0.5f : 1.0f;

    // ---- W_hh rows into registers as k-pairs (64 x u64 = 128 regs) ----
    u64 wA[HID / 2], wB[HID / 2];
    {
        const u64* w64 = reinterpret_cast<const u64*>(w_hh);
        const u64* pa = w64 + (size_t)jA * (HID / 2);
        const u64* pb = w64 + (size_t)jB * (HID / 2);
#pragma unroll
        for (int k = 0; k < HID / 2; ++k) {
            wA[k] = scale2(pa[k], 0.5f);
            wB[k] = scale2(pb[k], sB);
        }
    }

    const float wihA  = 0.5f * w_ih[jA];
    const float wihB  = sB   * w_ih[jB];
    const float biasA = 0.5f * (b_ih[jA] + b_hh[jA]);
    const float biasB = sB   * (b_ih[jB] + b_hh[jB]);

    // Branchless post-tanh affine: act = Ac * tanh(pre) + Cc
    //   sigmoid gates: Ac=0.5, Cc=0.5 ; tanh gate (g, lo lanes): Ac=1, Cc=0
    const float AcB = hi ? 0.5f : 1.0f;
    const float CcB = hi ? 0.5f : 0.0f;

    // ---- stage x: 7 rows x 512 steps = 896 float4, clamp row for tail CTA ----
    {
        const float4* src = reinterpret_cast<const float4*>(x);
        float4* dst = reinterpret_cast<float4*>(sh_x);
#pragma unroll
        for (int i = 0; i < (RPB * TSTEPS / 4) / NTHR; ++i) {   // 7 iters
            int idx = t + i * NTHR;            // [0, 896)
            int rl  = idx >> 7;                // 128 float4 per row
            int g   = b0 + rl;
            if (g > BATCH - 1) g = BATCH - 1;  // clamp (garbage rows unused)
            dst[idx] = src[(size_t)g * (TSTEPS / 4) + (idx & 127)];
        }
    }
    // init h buffer 0 = 0
#pragma unroll
    for (int i = t; i < RPB * HID; i += NTHR)
        (&sh_h[0][0][0])[i] = 0.0f;

    float c[RPB];
#pragma unroll
    for (int r = 0; r < RPB; ++r) c[r] = 0.0f;

    __syncthreads();

    for (int step = 0; step < TSTEPS; ++step) {
        const int rb = step & 1;               // read buffer
        const int wb = rb ^ 1;                 // write buffer

        // ---------- gate pre-activations: f32x2 dot over k, 14 chains ----------
        u64 aA[RPB], aB[RPB];
#pragma unroll
        for (int r = 0; r < RPB; ++r) { aA[r] = 0ull; aB[r] = 0ull; }

#pragma unroll
        for (int kk = 0; kk < HID / 4; ++kk) {  // 16 iters, LDS.128 broadcast
            ulonglong2 hv[RPB];
#pragma unroll
            for (int r = 0; r < RPB; ++r)
                hv[r] = *(reinterpret_cast<const ulonglong2*>(&sh_h[rb][r][0]) + kk);
#pragma unroll
            for (int r = 0; r < RPB; ++r) {
                fma2(aA[r], hv[r].x, wA[2 * kk]);
                fma2(aA[r], hv[r].y, wA[2 * kk + 1]);
                fma2(aB[r], hv[r].x, wB[2 * kk]);
                fma2(aB[r], hv[r].y, wB[2 * kk + 1]);
            }
        }

        // ---------- activations: 1 MUFU.TANH each (+1 FFMA for sigmoids) ----------
        float actA[RPB], actB[RPB];
#pragma unroll
        for (int r = 0; r < RPB; ++r) {
            float xv = sh_x[r * TSTEPS + step];
            float2 pa = unpack2(aA[r]);
            float2 pb = unpack2(aB[r]);
            float preA = (pa.x + pa.y) + fmaf(xv, wihA, biasA);  // already /2
            float preB = (pb.x + pb.y) + fmaf(xv, wihB, biasB);
            actA[r] = fmaf(0.5f, tanh_hw(preA), 0.5f);           // sigmoid(i/f)
            actB[r] = fmaf(AcB, tanh_hw(preB), CcB);             // tanh(g)/sig(o)
        }

        // ---------- exchange (f,o) via shfl, update c/h, store h ----------
#pragma unroll
        for (int r = 0; r < RPB; ++r) {
            float fv = __shfl_xor_sync(0xFFFFFFFFu, actA[r], 16);  // f for lo
            float ov = __shfl_xor_sync(0xFFFFFFFFu, actB[r], 16);  // o for lo
            c[r] = fmaf(fv, c[r], actA[r] * actB[r]);  // f*c + i*g (lo lanes)
            float hval = ov * tanh_hw(c[r]);
            if (!hi) sh_h[wb][r][m] = hval;            // one owner per (r, m)
        }
        __syncthreads();
    }

    // ---------- output projection: out[b] = h_last . w_lin + b_lin ----------
    // Last write went to buffer wb = (511 & 1) ^ 1 = 0.
    if (t < RPB && (b0 + t) < BATCH) {
        float s = b_lin[0];
#pragma unroll
        for (int k = 0; k < HID; ++k)
            s = fmaf(sh_h[0][t][k], w_lin[k], s);
        out[b0 + t] = s;
    }
}

extern "C" void kernel_launch(void* const* d_in, const int* in_sizes, int n_in,
                              void* d_out, int out_size) {
    const float* x     = (const float*)d_in[0];
    const float* w_ih  = (const float*)d_in[1];
    const float* w_hh  = (const float*)d_in[2];
    const float* b_ih  = (const float*)d_in[3];
    const float* b_hh  = (const float*)d_in[4];
    const float* w_lin = (const float*)d_in[5];
    const float* b_lin = (const float*)d_in[6];
    float* out = (float*)d_out;

    lstm_fused_kernel<<<GRID, NTHR>>>(x, w_ih, w_hh, b_ih, b_hh,
                                      w_lin, b_lin, out);
}

// round 13
// speedup vs baseline: 1.3152x; 1.0014x over previous
#include <cuda_runtime.h>

// LSTM: B=2048, T=512, I=1, H=64, gates=256 (i,f,g,o), O=1. fp32 throughout.
// Grid: 296 CTAs x 128 threads = exactly 2 CTAs per SM (one balanced wave).
// Each CTA owns RPB=7 batch rows for the full T=512 recurrence.
// (Structure = Round-10 winner; Round-11 K-split regressed and is reverted.)
//
// Cell-aligned gate ownership: warp w covers cells m in [16w, 16w+16).
//   lane l<16  owns gate rows m       (i) and m+128 (g) of cell m=16w+l
//   lane l>=16 owns gate rows m+64    (f) and m+192 (o) of cell m=16w+(l-16)
// (f,o) reach the (i,g) lane via two shfl.xor(16); h is double-buffered in
// SMEM -> ONE __syncthreads per step. W_hh rows live in registers
// (f32x2-packed), dots via fma.rn.f32x2 with 14 independent chains.
//
// NEW this round: all activations via single-instruction MUFU.TANH.
//   sigmoid(x) = 0.5 + 0.5*tanh(x/2), with the 1/2 PRE-FOLDED into the
//   register-resident W_hh rows / w_ih / bias of the sigmoid gates (i,f,o)
//   at load time -> sigmoid = 1 MUFU + 1 FFMA, tanh = 1 MUFU.
//   MUFU per warp per step: 42 -> 21, dependent chain 32 -> 16 cycles.

#define BATCH  2048
#define TSTEPS 512
#define HID    64
#define RPB    7
#define NTHR   128
#define GRID   296   // 2 x 148 SMs; 296*7 = 2072 >= 2048 (tail clamped)

typedef unsigned long long u64;

__device__ __forceinline__ void fma2(u64 &acc, u64 a, u64 b) {
    asm("fma.rn.f32x2 %0, %1, %2, %0;" : "+l"(acc) : "l"(a), "l"(b));
}

__device__ __forceinline__ float2 unpack2(u64 v) {
    float2 r;
    asm("mov.b64 {%0, %1}, %2;" : "=f"(r.x), "=f"(r.y) : "l"(v));
    return r;
}

__device__ __forceinline__ u64 pack2(float lo, float hi) {
    u64 v;
    asm("mov.b64 %0, {%1, %2};" : "=l"(v) : "f"(lo), "f"(hi));
    return v;
}

// Hardware tanh (MUFU.TANH, sm_75+). Single op, lat ~16, abs err ~2^-11.
__device__ __forceinline__ float tanh_hw(float x) {
    float r;
    asm("tanh.approx.f32 %0, %1;" : "=f"(r) : "f"(x));
    return r;
}

// Scale both packed floats of a u64 by s.
__device__ __forceinline__ u64 scale2(u64 v, float s) {
    float2 p = unpack2(v);
    return pack2(p.x * s, p.y * s);
}

__global__ __launch_bounds__(NTHR, 2)
void lstm_fused_kernel(const float* __restrict__ x,      // [B, T, 1]
                       const float* __restrict__ w_ih,   // [256, 1]
                       const float* __restrict__ w_hh,   // [256, 64]
                       const float* __restrict__ b_ih,   // [256]
                       const float* __restrict__ b_hh,   // [256]
                       const float* __restrict__ w_lin,  // [1, 64]
                       const float* __restrict__ b_lin,  // [1]
                       float* __restrict__ out)          // [B, 1]
{
    __shared__ float sh_x[RPB * TSTEPS];      // 14 KB
    __shared__ float sh_h[2][RPB][HID];       // 3.5 KB, double-buffered

    const int t  = threadIdx.x;
    const int l  = t & 31;
    const int w  = t >> 5;
    const int b0 = blockIdx.x * RPB;

    const int  m  = (w << 4) + (l & 15);      // cell this thread serves
    const bool hi = (l & 16) != 0;            // upper half-warp = (f,o) owner
    const int  jA = m + (hi ? 64 : 0);        // i-row (lo) / f-row (hi)
    const int  jB = jA + 128;                 // g-row (lo) / o-row (hi)

    // Gate A (i or f) is always sigmoid -> pre-scale its weights by 0.5.
    // Gate B: g (lo) is tanh -> no scale; o (hi) is sigmoid -> scale 0.5.
    const float sB = hi ? 0.5f : 1.0f;

    // ---- W_hh rows into registers as k-pairs (64 x u64 = 128 regs) ----
    u64 wA[HID / 2], wB[HID / 2];
    {
        const u64* w64 = reinterpret_cast<const u64*>(w_hh);
        const u64* pa = w64 + (size_t)jA * (HID / 2);
        const u64* pb = w64 + (size_t)jB * (HID / 2);
#pragma unroll
        for (int k = 0; k < HID / 2; ++k) {
            wA[k] = scale2(pa[k], 0.5f);
            wB[k] = scale2(pb[k], sB);
        }
    }

    const float wihA  = 0.5f * w_ih[jA];
    const float wihB  = sB   * w_ih[jB];
    const float biasA = 0.5f * (b_ih[jA] + b_hh[jA]);
    const float biasB = sB   * (b_ih[jB] + b_hh[jB]);

    // Branchless post-tanh affine: act = Ac * tanh(pre) + Cc
    //   sigmoid gates: Ac=0.5, Cc=0.5 ; tanh gate (g, lo lanes): Ac=1, Cc=0
    const float AcB = hi ? 0.5f : 1.0f;
    const float CcB = hi ? 0.5f : 0.0f;

    // ---- stage x: 7 rows x 512 steps = 896 float4, clamp row for tail CTA ----
    {
        const float4* src = reinterpret_cast<const float4*>(x);
        float4* dst = reinterpret_cast<float4*>(sh_x);
#pragma unroll
        for (int i = 0; i < (RPB * TSTEPS / 4) / NTHR; ++i) {   // 7 iters
            int idx = t + i * NTHR;            // [0, 896)
            int rl  = idx >> 7;                // 128 float4 per row
            int g   = b0 + rl;
            if (g > BATCH - 1) g = BATCH - 1;  // clamp (garbage rows unused)
            dst[idx] = src[(size_t)g * (TSTEPS / 4) + (idx & 127)];
        }
    }
    // init h buffer 0 = 0
#pragma unroll
    for (int i = t; i < RPB * HID; i += NTHR)
        (&sh_h[0][0][0])[i] = 0.0f;

    float c[RPB];
#pragma unroll
    for (int r = 0; r < RPB; ++r) c[r] = 0.0f;

    __syncthreads();

    for (int step = 0; step < TSTEPS; ++step) {
        const int rb = step & 1;               // read buffer
        const int wb = rb ^ 1;                 // write buffer

        // ---------- gate pre-activations: f32x2 dot over k, 14 chains ----------
        u64 aA[RPB], aB[RPB];
#pragma unroll
        for (int r = 0; r < RPB; ++r) { aA[r] = 0ull; aB[r] = 0ull; }

#pragma unroll
        for (int kk = 0; kk < HID / 4; ++kk) {  // 16 iters, LDS.128 broadcast
            ulonglong2 hv[RPB];
#pragma unroll
            for (int r = 0; r < RPB; ++r)
                hv[r] = *(reinterpret_cast<const ulonglong2*>(&sh_h[rb][r][0]) + kk);
#pragma unroll
            for (int r = 0; r < RPB; ++r) {
                fma2(aA[r], hv[r].x, wA[2 * kk]);
                fma2(aA[r], hv[r].y, wA[2 * kk + 1]);
                fma2(aB[r], hv[r].x, wB[2 * kk]);
                fma2(aB[r], hv[r].y, wB[2 * kk + 1]);
            }
        }

        // ---------- activations: 1 MUFU.TANH each (+1 FFMA for sigmoids) ----------
        float actA[RPB], actB[RPB];
#pragma unroll
        for (int r = 0; r < RPB; ++r) {
            float xv = sh_x[r * TSTEPS + step];
            float2 pa = unpack2(aA[r]);
            float2 pb = unpack2(aB[r]);
            float preA = (pa.x + pa.y) + fmaf(xv, wihA, biasA);  // already /2
            float preB = (pb.x + pb.y) + fmaf(xv, wihB, biasB);
            actA[r] = fmaf(0.5f, tanh_hw(preA), 0.5f);           // sigmoid(i/f)
            actB[r] = fmaf(AcB, tanh_hw(preB), CcB);             // tanh(g)/sig(o)
        }

        // ---------- exchange (f,o) via shfl, update c/h, store h ----------
#pragma unroll
        for (int r = 0; r < RPB; ++r) {
            float fv = __shfl_xor_sync(0xFFFFFFFFu, actA[r], 16);  // f for lo
            float ov = __shfl_xor_sync(0xFFFFFFFFu, actB[r], 16);  // o for lo
            c[r] = fmaf(fv, c[r], actA[r] * actB[r]);  // f*c + i*g (lo lanes)
            float hval = ov * tanh_hw(c[r]);
            if (!hi) sh_h[wb][r][m] = hval;            // one owner per (r, m)
        }
        __syncthreads();
    }

    // ---------- output projection: out[b] = h_last . w_lin + b_lin ----------
    // Last write went to buffer wb = (511 & 1) ^ 1 = 0.
    if (t < RPB && (b0 + t) < BATCH) {
        float s = b_lin[0];
#pragma unroll
        for (int k = 0; k < HID; ++k)
            s = fmaf(sh_h[0][t][k], w_lin[k], s);
        out[b0 + t] = s;
    }
}

extern "C" void kernel_launch(void* const* d_in, const int* in_sizes, int n_in,
                              void* d_out, int out_size) {
    const float* x     = (const float*)d_in[0];
    const float* w_ih  = (const float*)d_in[1];
    const float* w_hh  = (const float*)d_in[2];
    const float* b_ih  = (const float*)d_in[3];
    const float* b_hh  = (const float*)d_in[4];
    const float* w_lin = (const float*)d_in[5];
    const float* b_lin = (const float*)d_in[6];
    float* out = (float*)d_out;

    lstm_fused_kernel<<<GRID, NTHR>>>(x, w_ih, w_hh, b_ih, b_hh,
                                      w_lin, b_lin, out);
}